// round 5
// baseline (speedup 1.0000x reference)
#include <cuda_runtime.h>
#include <cstdint>

#define NWORDS  16384
#define LW      32
#define NC      64
#define E3      256
#define OUTW    770
#define W4S     65          // float4 stride per char row (padded)
#define ROWB    1040u       // bytes per char row = 65 * 16
#define NGROUPS 2048        // NWORDS / 8
#define NBLK    296         // 148 SMs * 2 resident blocks
#define BLOCKT  512         // two independent 256-thread halves

typedef unsigned long long ull;

static constexpr int SMEM_FLOATS = NC * W4S * 4;                    // 16640
// WT + per-half offsets [2][8][32] + per-half group slots [2][2]
static constexpr int SMEM_BYTES  = SMEM_FLOATS * 4 + 2 * 8 * LW * 4 + 16;

__device__ int g_ctr;

__global__ void reset_ctr() { g_ctr = 0; }

__device__ __forceinline__ void lds128(uint32_t addr, ull &a, ull &b) {
    asm("ld.shared.v2.b64 {%0,%1}, [%2];" : "=l"(a), "=l"(b) : "r"(addr));
}
__device__ __forceinline__ ull add2(ull a, ull b) {
    ull r; asm("add.rn.f32x2 %0, %1, %2;" : "=l"(r) : "l"(a), "l"(b)); return r;
}

__global__ __launch_bounds__(BLOCKT, 2) void opb_kernel(
    const int* __restrict__ sntcs, const float* __restrict__ W,
    float* __restrict__ out)
{
    extern __shared__ float smem[];
    float*    sWT   = smem;                                  // [64][65] float4 rows
    uint32_t* sOffs = (uint32_t*)(smem + SMEM_FLOATS);       // [2][8][32]
    volatile int* sG = (volatile int*)(sOffs + 2 * 8 * LW);  // [2][2] ping-pong

    const int tid  = threadIdx.x;
    const int half = tid >> 8;          // 0 or 1: independent 256-thread half
    const int htid = tid & 255;
    const int lane = tid & 31;
    const int wj   = htid >> 5;         // metadata: warp per word (0..7)
    const int team = (htid >> 6) & 3;   // gather: 64-thread team (0..3)
    const int et   = htid & 63;         // float4 column owned by this thread

    // ---- Fill shared WT once per block (shared by both halves) ----
    for (int idx = tid; idx < E3 * NC; idx += BLOCKT) {
        int e = idx >> 6, c = idx & 63;
        sWT[c * (W4S * 4) + e] = W[idx];
    }
    if (htid == 0) sG[half * 2] = atomicAdd(&g_ctr, 1);   // prologue grab
    __syncthreads();

    uint32_t sbase;
    asm("{ .reg .u64 t; cvta.to.shared.u64 t, %1; cvt.u32.u64 %0, t; }"
        : "=r"(sbase) : "l"(smem));
    const uint32_t gbase = sbase + (uint32_t)et * 16u;

    for (int it = 0; ; ++it) {
        const int g = sG[half * 2 + (it & 1)];
        if (g >= NGROUPS) break;

        // ---- metadata: one warp per word; first-occurrence argmax ----
        {
            int c = sntcs[(g * 8 + wj) * LW + lane];
            unsigned key = ((unsigned)c << 5) | (unsigned)(31 - lane);
            #pragma unroll
            for (int off = 16; off; off >>= 1) {
                unsigned o = __shfl_xor_sync(0xffffffffu, key, off);
                key = key > o ? key : o;
            }
            int p  = 31 - (int)(key & 31u);            // argmax (first max)
            int wl = p - 1; if (wl < 0) wl = 0;        // relu(argmax - 1)
            int ends = __shfl_sync(0xffffffffu, c, wl);   // gather BEFORE scatter
            int s = (lane == wl) ? 0 : c;              // scatter 0 at wl
            if (lane == 31) s = ends;                  // overwrite last with ends
            sOffs[(half * 8 + wj) * LW + lane] = (uint32_t)s * ROWB;
        }
        if (htid == 0)                                  // grab NEXT group now;
            sG[half * 2 + ((it + 1) & 1)] = atomicAdd(&g_ctr, 1);  // latency hidden

        asm volatile("bar.sync %0, %1;" :: "r"(half + 1), "r"(256) : "memory");

        // ---- gather: 4 teams x 2 words, single-word streams (R2 shape) ----
        #pragma unroll
        for (int jj = 0; jj < 2; jj++) {
            const int j = team * 2 + jj;
            const uint4* op = (const uint4*)(sOffs + (half * 8 + j) * LW);

            ull f01 = 0, f23 = 0, l01 = 0, l23 = 0;
            ull a01 = 0, a23 = 0, b01 = 0, b23 = 0;

            #pragma unroll
            for (int k = 0; k < 8; k++) {
                uint4 ck = op[k];                      // broadcast LDS.128
                #pragma unroll
                for (int q = 0; q < 4; q++) {
                    const int l = 4 * k + q;
                    uint32_t off4 = (q == 0) ? ck.x : (q == 1) ? ck.y
                                  : (q == 2) ? ck.z : ck.w;
                    ull v01, v23;
                    lds128(gbase + off4, v01, v23);
                    if (l == 0)            { f01 = v01; f23 = v23; }
                    else if (l == LW - 1)  { l01 = v01; l23 = v23; }
                    else if (l & 1)        { a01 = add2(a01, v01); a23 = add2(a23, v23); }
                    else                   { b01 = add2(b01, v01); b23 = add2(b23, v23); }
                }
            }
            ull s01 = add2(a01, b01), s23 = add2(a23, b23);

            const int w = g * 8 + j;
            float* o = out + (size_t)w * OUTW + 4 * et;
            *(ull*)(o + 2)        = f01;   // first (base+2: 8B aligned)
            *(ull*)(o + 4)        = f23;
            *(ull*)(o + 2 + E3)   = s01;   // bow
            *(ull*)(o + 4 + E3)   = s23;
            *(ull*)(o + 2 + 2*E3) = l01;   // last
            *(ull*)(o + 4 + 2*E3) = l23;
            if (et == 0) *(ull*)(out + (size_t)w * OUTW) = 0ull;  // left pad
        }
        asm volatile("bar.sync %0, %1;" :: "r"(half + 1), "r"(256) : "memory");
    }
}

extern "C" void kernel_launch(void* const* d_in, const int* in_sizes, int n_in,
                              void* d_out, int out_size)
{
    const int*   sntcs = (const int*)d_in[0];
    const float* W     = (const float*)d_in[1];
    float*       out   = (float*)d_out;

    cudaFuncSetAttribute(opb_kernel, cudaFuncAttributeMaxDynamicSharedMemorySize, SMEM_BYTES);
    reset_ctr<<<1, 1>>>();
    opb_kernel<<<NBLK, BLOCKT, SMEM_BYTES>>>(sntcs, W, out);
}